// round 3
// baseline (speedup 1.0000x reference)
#include <cuda_runtime.h>
#include <math.h>

#define WPB   8
#define NLAB  17
#define LTOT  19
#define SEQ   256
#define MAXB  8192

__device__ int d_cursor[SEQ];      // per-length write cursor (rebuilt every call)
__device__ int d_sorted[MAXB];     // row indices, descending length

// BIOES predecessor lists, T indexed [to][from]. Pads -> column 18 (weight 0).
__constant__ signed char PREDS[17][9] = {
  {0,3,4,7,8,11,12,15,16},
  {0,3,4,7,8,11,12,15,16},
  {1,2,18,18,18,18,18,18,18},
  {1,2,18,18,18,18,18,18,18},
  {0,3,4,7,8,11,12,15,16},
  {0,3,4,7,8,11,12,15,16},
  {5,6,18,18,18,18,18,18,18},
  {5,6,18,18,18,18,18,18,18},
  {0,3,4,7,8,11,12,15,16},
  {0,3,4,7,8,11,12,15,16},
  {9,10,18,18,18,18,18,18,18},
  {9,10,18,18,18,18,18,18,18},
  {0,3,4,7,8,11,12,15,16},
  {0,3,4,7,8,11,12,15,16},
  {13,14,18,18,18,18,18,18,18},
  {13,14,18,18,18,18,18,18,18},
  {0,3,4,7,8,11,12,15,16},
};

// K1: one block. Histogram of lens (1..SEQ) + suffix scan -> d_cursor[len-1]
// = number of rows strictly longer than len (start rank for that length bin).
__global__ void crf_sched_hist(const int* __restrict__ lens, int B)
{
    __shared__ int h[SEQ];
    int t = threadIdx.x;
    h[t] = 0;
    __syncthreads();
    for (int i = t; i < B; i += blockDim.x)
        atomicAdd(&h[lens[i] - 1], 1);
    __syncthreads();
    int s = 0;
    for (int k = t + 1; k < SEQ; ++k) s += h[k];
    d_cursor[t] = s;
}

// K2: scatter rows into descending-length order.
__global__ void crf_sched_scatter(const int* __restrict__ lens, int B)
{
    int i = blockIdx.x * blockDim.x + threadIdx.x;
    if (i < B) {
        int r = atomicAdd(&d_cursor[lens[i] - 1], 1);
        d_sorted[r] = i;
    }
}

// Main: one warp per row; lane j<17 owns state j; exp-domain forward with
// exact 2^-e rescaling every 4 steps; sparse 9-pred transition via shfl.idx.
// Warp w of block b takes rank b + w*gridDim -> every block gets an even
// spread of lengths (balanced makespan across SMs).
__global__ __launch_bounds__(32 * WPB)
void crf_fwd_kernel(const float* __restrict__ logits,
                    const int*   __restrict__ labels,
                    const int*   __restrict__ lens,
                    const float* __restrict__ transition,
                    float* __restrict__ out, int B)
{
    __shared__ float sT[LTOT * LTOT];
    for (int i = threadIdx.x; i < LTOT * LTOT; i += blockDim.x)
        sT[i] = transition[i];
    __syncthreads();

    const int lane = threadIdx.x & 31;
    const int warp = threadIdx.x >> 5;
    const int rank = blockIdx.x + warp * gridDim.x;
    if (rank >= B) return;
    const int b = d_sorted[rank];

    const int    len = lens[b];
    const int*   lab = labels + (size_t)b * SEQ;
    const float* lg  = logits + (size_t)b * (SEQ * NLAB);

    // ---------------- gold score (parallel over t) -------------------------
    float g = 0.f;
    for (int t = lane; t < len; t += 32) {
        int lt = lab[t];
        int lp = (t == 0) ? (LTOT - 2) : lab[t - 1];
        g += lg[t * NLAB + lt] + sT[lt * LTOT + lp];
    }
    if (lane == 0) g += sT[(LTOT - 1) * LTOT + lab[len - 1]];
    #pragma unroll
    for (int o = 16; o; o >>= 1) g += __shfl_xor_sync(0xffffffffu, g, o);

    // ---------------- per-lane sparse weights ------------------------------
    float w[9];
    int   src[9];
    #pragma unroll
    for (int k = 0; k < 9; ++k) { w[k] = 0.f; src[k] = 18; }
    float wstart = 0.f, wend = 0.f;
    if (lane < NLAB) {
        #pragma unroll
        for (int k = 0; k < 9; ++k) {
            int pr = PREDS[lane][k];
            src[k] = pr;
            w[k]   = expf(sT[lane * LTOT + pr]);   // pads -> exp(-1e4) = 0
        }
        wstart = expf(sT[lane * LTOT + 17]);
        wend   = expf(sT[18 * LTOT + lane]);
    }

    // lane-clamped logit pointer (lanes >= 17 read a dummy in-bounds column)
    const float* lgp = lg + ((lane < NLAB) ? lane : (NLAB - 1));

    // ---------------- t = 0 -------------------------------------------------
    float p = __expf(lgp[0]) * wstart;
    int   C = 0;
    {
        unsigned m  = __reduce_max_sync(0xffffffffu, __float_as_uint(p));
        int eb = (int)(m >> 23);
        p *= __uint_as_float((unsigned)(254 - eb) << 23);
        C += eb - 127;
    }
    const float* pf = lgp + NLAB;         // prefetch pointer (t = 1)
    float enext = __expf(*pf);

    // ---------------- forward recursion ------------------------------------
    #pragma unroll 4
    for (int t = 1; t < len; ++t) {
        float ecur = enext;
        if (t + 1 < SEQ) {                // stale enext unused at loop exit
            pf += NLAB;
            enext = __expf(*pf);
        }

        float q0 = __shfl_sync(0xffffffffu, p, src[0]);
        float q1 = __shfl_sync(0xffffffffu, p, src[1]);
        float q2 = __shfl_sync(0xffffffffu, p, src[2]);
        float q3 = __shfl_sync(0xffffffffu, p, src[3]);
        float q4 = __shfl_sync(0xffffffffu, p, src[4]);
        float q5 = __shfl_sync(0xffffffffu, p, src[5]);
        float q6 = __shfl_sync(0xffffffffu, p, src[6]);
        float q7 = __shfl_sync(0xffffffffu, p, src[7]);
        float q8 = __shfl_sync(0xffffffffu, p, src[8]);

        float a0 = w[0] * q0;
        float a1 = w[1] * q1;
        float a2 = w[2] * q2;
        a0 = fmaf(w[3], q3, a0);
        a1 = fmaf(w[4], q4, a1);
        a2 = fmaf(w[5], q5, a2);
        a0 = fmaf(w[6], q6, a0);
        a1 = fmaf(w[7], q7, a1);
        a2 = fmaf(w[8], q8, a2);
        p = ecur * ((a0 + a1) + a2);

        if ((t & 3) == 0) {
            unsigned m  = __reduce_max_sync(0xffffffffu, __float_as_uint(p));
            int eb = (int)(m >> 23);
            p *= __uint_as_float((unsigned)(254 - eb) << 23);
            C += eb - 127;
        }
    }

    // ---------------- finalize ----------------------------------------------
    float s = p * wend;
    #pragma unroll
    for (int o = 16; o; o >>= 1) s += __shfl_xor_sync(0xffffffffu, s, o);

    if (lane == 0)
        out[b] = g - ((float)C * 0.69314718055994531f + logf(s));
}

extern "C" void kernel_launch(void* const* d_in, const int* in_sizes, int n_in,
                              void* d_out, int out_size)
{
    const float* logits     = (const float*)d_in[0];
    const int*   labels     = (const int*)  d_in[1];
    const int*   lens       = (const int*)  d_in[2];
    const float* transition = (const float*)d_in[3];
    float*       out        = (float*)d_out;

    int B = in_sizes[2];

    crf_sched_hist<<<1, SEQ>>>(lens, B);
    crf_sched_scatter<<<(B + 255) / 256, 256>>>(lens, B);

    int grid = (B + WPB - 1) / WPB;
    crf_fwd_kernel<<<grid, 32 * WPB>>>(logits, labels, lens, transition, out, B);
}